// round 3
// baseline (speedup 1.0000x reference)
#include <cuda_runtime.h>
#include <math.h>
#include <float.h>

#define Bq 64
#define Nq 16384
#define Mq 64
#define Cq 256
#define GAMMAq 0.95f
#define EPSq 1e-16f
#define NOUT 66  // M + 2

// ---------------- scratch (static device globals; no allocation) ----------------
__device__ float g_k[Bq * Mq];
__device__ float g_beta[Bq];
__device__ float g_gate[Bq];
__device__ float g_sim[(size_t)Bq * Nq];

// ---------------- kernel 1: projection, warp per (batch, output) ----------------
// 4224 warps total = 528 blocks x 256 threads. Every dot product independent ->
// all memory latency overlapped in a single wave.
__global__ void ntm_proj_kernel(const float* __restrict__ emb,
                                const float* __restrict__ W,
                                const float* __restrict__ bias) {
    const int wglob = (blockIdx.x * blockDim.x + threadIdx.x) >> 5;
    const int lane = threadIdx.x & 31;
    if (wglob >= Bq * NOUT) return;
    const int b = wglob / NOUT;
    const int o = wglob - b * NOUT;

    const float* __restrict__ e = emb + (size_t)b * Cq;
    const float* __restrict__ w = W + (size_t)o * Cq;

    float acc = 0.0f;
#pragma unroll
    for (int i = 0; i < 8; i++) {
        const int c = lane + 32 * i;
        acc = fmaf(__ldg(&e[c]), __ldg(&w[c]), acc);
    }
#pragma unroll
    for (int s = 16; s > 0; s >>= 1)
        acc += __shfl_xor_sync(0xffffffffu, acc, s);

    if (lane == 0) {
        acc += bias[o];
        if (o < Mq) {
            g_k[b * Mq + o] = acc;
        } else if (o == Mq) {
            g_beta[b] = (acc > 20.0f) ? acc : log1pf(expf(acc));
        } else {
            g_gate[b] = 1.0f / (1.0f + expf(-acc));
        }
    }
}

// ---------------- kernel 2: fused sim + new_memory streaming pass ---------------
// grid: (Nq/64, Bq), block: 256 threads (8 warps).
// Each half-warp (16 lanes, float4 each) owns one memory row of M=64 floats.
// sim values staged in smem and written coalesced (float4) to avoid 8x sector
// amplification from per-row scalar stores.
__global__ void ntm_stream_kernel(const float* __restrict__ memory,
                                  const float* __restrict__ w_prev,
                                  float* __restrict__ out) {
    const int b = blockIdx.y;
    const int n0 = blockIdx.x * 64;
    const int tid = threadIdx.x;
    const int warp = tid >> 5;
    const int lane = tid & 31;
    const int sub = lane >> 4;
    const int l16 = lane & 15;

    __shared__ float4 sh_k4[16];
    __shared__ float sh_ww[64];
    __shared__ float sh_sim[64];
    __shared__ float s_knorm;

    const float gv = g_gate[b];

    // warp 0: load k, compute ||k|| with an in-warp reduce (no extra barrier)
    float kn = 0.0f;
    if (tid < 16) {
        const float4 k4 = ((const float4*)(g_k + (size_t)b * Mq))[tid];
        sh_k4[tid] = k4;
        kn = k4.x * k4.x + k4.y * k4.y + k4.z * k4.z + k4.w * k4.w;
    }
    if (tid < 32) {
#pragma unroll
        for (int s = 8; s > 0; s >>= 1)
            kn += __shfl_xor_sync(0xffffffffu, kn, s);
        if (tid == 0) s_knorm = sqrtf(kn);
    }
    if (tid < 64) {
        const int n = n0 + tid;
        const float wrp  = w_prev[((size_t)b * 3 + 1) * Nq + n];
        const float wlup = w_prev[((size_t)b * 3 + 2) * Nq + n];
        sh_ww[tid] = gv * wrp + (1.0f - gv) * wlup;
    }
    __syncthreads();

    const float knorm = s_knorm;
    const float4 kv = sh_k4[l16];
    float* __restrict__ newmem = out + (size_t)Bq * 3 * Nq;
    const float4* __restrict__ mem4 = (const float4*)memory;
    float4* __restrict__ out4 = (float4*)newmem;

#pragma unroll
    for (int r = 0; r < 4; r++) {
        const int local = warp * 8 + r * 2 + sub;  // 0..63
        const int n = n0 + local;
        const size_t off = ((size_t)b * Nq + n) * (Mq / 4) + l16;

        const float4 m = __ldcs(&mem4[off]);          // streaming read
        float dot = m.x * kv.x + m.y * kv.y + m.z * kv.z + m.w * kv.w;
        float nrm = m.x * m.x + m.y * m.y + m.z * m.z + m.w * m.w;
#pragma unroll
        for (int s = 8; s > 0; s >>= 1) {
            dot += __shfl_xor_sync(0xffffffffu, dot, s);
            nrm += __shfl_xor_sync(0xffffffffu, nrm, s);
        }

        const float ww = sh_ww[local];
        float4 o4;
        o4.x = m.x + ww * kv.x;
        o4.y = m.y + ww * kv.y;
        o4.z = m.z + ww * kv.z;
        o4.w = m.w + ww * kv.w;
        __stcs(&out4[off], o4);                        // streaming write

        if (l16 == 0)
            sh_sim[local] = dot / (knorm * sqrtf(nrm) + EPSq);
    }
    __syncthreads();

    // coalesced sim write: 16 threads x float4 = 64 floats
    if (tid < 16)
        ((float4*)(g_sim + (size_t)b * Nq + n0))[tid] =
            ((const float4*)sh_sim)[tid];
}

// ---------------- kernel 3: softmax + w_u + top-4 smallest (w_lu) ---------------
// grid: Bq blocks, 1024 threads (32 warps); each thread owns 16 strided elements.
__global__ void __launch_bounds__(1024, 1)
ntm_softmax_topk_kernel(const float* __restrict__ w_prev,
                        float* __restrict__ out) {
    const int b = blockIdx.x;
    const int tid = threadIdx.x;
    const int warp = tid >> 5;
    const int lane = tid & 31;

    __shared__ float sh_f[32];
    __shared__ unsigned long long sh_u[32];
    __shared__ float s_mx, s_sum;
    __shared__ unsigned long long s_win;
    __shared__ int s_chosen[4];

    const float beta = g_beta[b];
    const float gv   = g_gate[b];
    const float* __restrict__ simp = g_sim + (size_t)b * Nq;

    // ---- load sim, block max of beta*sim ----
    float sim[16];
    float lmax = -FLT_MAX;
#pragma unroll
    for (int j = 0; j < 16; j++) {
        const float s = simp[j * 1024 + tid];
        sim[j] = s;
        lmax = fmaxf(lmax, beta * s);
    }
#pragma unroll
    for (int s = 16; s > 0; s >>= 1)
        lmax = fmaxf(lmax, __shfl_xor_sync(0xffffffffu, lmax, s));
    if (lane == 0) sh_f[warp] = lmax;
    __syncthreads();
    if (tid < 32) {
        float v = sh_f[tid];
#pragma unroll
        for (int s = 16; s > 0; s >>= 1)
            v = fmaxf(v, __shfl_xor_sync(0xffffffffu, v, s));
        if (tid == 0) s_mx = v;
    }
    __syncthreads();
    const float mx = s_mx;

    // ---- block sum of exp ----
    float e[16];
    float lsum = 0.0f;
#pragma unroll
    for (int j = 0; j < 16; j++) {
        e[j] = expf(beta * sim[j] - mx);
        lsum += e[j];
    }
#pragma unroll
    for (int s = 16; s > 0; s >>= 1)
        lsum += __shfl_xor_sync(0xffffffffu, lsum, s);
    if (lane == 0) sh_f[warp] = lsum;
    __syncthreads();
    if (tid < 32) {
        float v = sh_f[tid];
#pragma unroll
        for (int s = 16; s > 0; s >>= 1)
            v += __shfl_xor_sync(0xffffffffu, v, s);
        if (tid == 0) s_sum = v;
    }
    __syncthreads();
    const float inv = 1.0f / s_sum;

    // ---- w_r, w_u, local top-4 smallest (packed keys: w_u>0 so float bits
    //      are order-preserving; low 32 bits = index for the top_k tiebreak) ----
    const float* __restrict__ wup  = w_prev + (size_t)b * 3 * Nq;
    const float* __restrict__ wrp  = wup + Nq;
    const float* __restrict__ wlup = wup + 2 * Nq;
    float* __restrict__ w_u_out  = out + (size_t)b * 3 * Nq;
    float* __restrict__ w_r_out  = w_u_out + Nq;
    float* __restrict__ w_lu_out = w_u_out + 2 * Nq;

    unsigned long long tk[4] = {~0ULL, ~0ULL, ~0ULL, ~0ULL};

#pragma unroll
    for (int j = 0; j < 16; j++) {
        const int n = j * 1024 + tid;
        const float wr = e[j] * inv;
        const float ww = gv * wrp[n] + (1.0f - gv) * wlup[n];
        const float wu = GAMMAq * wup[n] + wr + ww;
        w_r_out[n] = wr;
        w_u_out[n] = wu;

        const unsigned long long key =
            ((unsigned long long)__float_as_uint(wu) << 32) | (unsigned int)n;
        if (key < tk[3]) {
            tk[3] = key;
#pragma unroll
            for (int q = 3; q > 0; q--) {
                if (tk[q] < tk[q - 1]) {
                    unsigned long long t = tk[q]; tk[q] = tk[q - 1]; tk[q - 1] = t;
                }
            }
        }
    }

    // ---- 4 rounds of block argmin over per-thread sorted heads ----
    for (int round = 0; round < 4; round++) {
        unsigned long long my = tk[0];
#pragma unroll
        for (int s = 16; s > 0; s >>= 1) {
            const unsigned long long o = __shfl_xor_sync(0xffffffffu, my, s);
            if (o < my) my = o;
        }
        if (lane == 0) sh_u[warp] = my;
        __syncthreads();
        if (tid < 32) {
            unsigned long long v = sh_u[tid];
#pragma unroll
            for (int s = 16; s > 0; s >>= 1) {
                const unsigned long long o = __shfl_xor_sync(0xffffffffu, v, s);
                if (o < v) v = o;
            }
            if (tid == 0) s_win = v;
        }
        __syncthreads();
        const unsigned long long win = s_win;
        if (tid == 0) s_chosen[round] = (int)(unsigned int)(win & 0xffffffffu);
        if (tk[0] == win) {  // unique index -> exactly one popper
            tk[0] = tk[1]; tk[1] = tk[2]; tk[2] = tk[3]; tk[3] = ~0ULL;
        }
        __syncthreads();
    }

    const int c0 = s_chosen[0], c1 = s_chosen[1], c2 = s_chosen[2], c3 = s_chosen[3];
#pragma unroll
    for (int j = 0; j < 16; j++) {
        const int n = j * 1024 + tid;
        w_lu_out[n] = (n == c0 || n == c1 || n == c2 || n == c3) ? 1.0f : 0.0f;
    }
}

// ---------------- launch ----------------
extern "C" void kernel_launch(void* const* d_in, const int* in_sizes, int n_in,
                              void* d_out, int out_size) {
    const float* emb    = (const float*)d_in[0];  // (64, 256)
    const float* w_prev = (const float*)d_in[1];  // (64, 3, 16384)
    const float* memory = (const float*)d_in[2];  // (64, 16384, 64)
    const float* W      = (const float*)d_in[3];  // (66, 256)
    const float* bias   = (const float*)d_in[4];  // (66,)
    float* out = (float*)d_out;  // [w (64*3*16384) | new_memory (64*16384*64)]

    const int nwarps = Bq * NOUT;             // 4224
    const int nblk1 = (nwarps * 32 + 255) / 256;  // 528
    ntm_proj_kernel<<<nblk1, 256>>>(emb, W, bias);

    dim3 grid2(Nq / 64, Bq);
    ntm_stream_kernel<<<grid2, 256>>>(memory, w_prev, out);

    ntm_softmax_topk_kernel<<<Bq, 1024>>>(w_prev, out);
}

// round 4
// speedup vs baseline: 1.1050x; 1.1050x over previous
#include <cuda_runtime.h>
#include <math.h>
#include <float.h>

#define Bq 64
#define Nq 16384
#define Mq 64
#define Cq 256
#define GAMMAq 0.95f
#define EPSq 1e-16f
#define NOUT 66  // M + 2

// ---------------- scratch (static device globals; no allocation) ----------------
__device__ float g_k[Bq * Mq];
__device__ float g_beta[Bq];
__device__ float g_gate[Bq];
__device__ float g_sim[(size_t)Bq * Nq];

// ---------------- kernel 1: projection, warp per (batch, output) ----------------
__global__ void ntm_proj_kernel(const float* __restrict__ emb,
                                const float* __restrict__ W,
                                const float* __restrict__ bias) {
    const int wglob = (blockIdx.x * blockDim.x + threadIdx.x) >> 5;
    const int lane = threadIdx.x & 31;
    if (wglob >= Bq * NOUT) return;
    const int b = wglob / NOUT;
    const int o = wglob - b * NOUT;

    const float* __restrict__ e = emb + (size_t)b * Cq;
    const float* __restrict__ w = W + (size_t)o * Cq;

    float acc = 0.0f;
#pragma unroll
    for (int i = 0; i < 8; i++) {
        const int c = lane + 32 * i;
        acc = fmaf(__ldg(&e[c]), __ldg(&w[c]), acc);
    }
#pragma unroll
    for (int s = 16; s > 0; s >>= 1)
        acc += __shfl_xor_sync(0xffffffffu, acc, s);

    if (lane == 0) {
        acc += bias[o];
        if (o < Mq) {
            g_k[b * Mq + o] = acc;
        } else if (o == Mq) {
            g_beta[b] = (acc > 20.0f) ? acc : log1pf(expf(acc));
        } else {
            g_gate[b] = 1.0f / (1.0f + expf(-acc));
        }
    }
}

// ---------------- kernel 2: fused sim + new_memory streaming pass ---------------
// grid: (Nq/128, Bq), block: 512 threads (32 half-warps).
// Half-warp hw owns rows {hw, hw+32, hw+64, hw+96} of a 128-row chunk.
// Phase A: batch all 4 LDG.128. Phase B: all 4 STG.128 (independent of reduces).
// Phase C: shfl reductions for dot/norm -> sim.
__global__ void __launch_bounds__(512)
ntm_stream_kernel(const float* __restrict__ memory,
                  const float* __restrict__ w_prev,
                  float* __restrict__ out) {
    const int b = blockIdx.y;
    const int n0 = blockIdx.x * 128;
    const int tid = threadIdx.x;
    const int hw = tid >> 4;       // half-warp id 0..31
    const int l16 = tid & 15;

    __shared__ float4 sh_k4[16];
    __shared__ float sh_ww[128];
    __shared__ float sh_sim[128];
    __shared__ float s_knorm;

    const float gv = g_gate[b];

    float kn = 0.0f;
    if (tid < 16) {
        const float4 k4 = ((const float4*)(g_k + (size_t)b * Mq))[tid];
        sh_k4[tid] = k4;
        kn = k4.x * k4.x + k4.y * k4.y + k4.z * k4.z + k4.w * k4.w;
    }
    if (tid < 32) {
#pragma unroll
        for (int s = 8; s > 0; s >>= 1)
            kn += __shfl_xor_sync(0xffffffffu, kn, s);
        if (tid == 0) s_knorm = sqrtf(kn);
    }
    if (tid < 128) {
        const int n = n0 + tid;
        const float wrp  = w_prev[((size_t)b * 3 + 1) * Nq + n];
        const float wlup = w_prev[((size_t)b * 3 + 2) * Nq + n];
        sh_ww[tid] = gv * wrp + (1.0f - gv) * wlup;
    }
    __syncthreads();

    const float knorm = s_knorm;
    const float4 kv = sh_k4[l16];
    float* __restrict__ newmem = out + (size_t)Bq * 3 * Nq;
    const float4* __restrict__ mem4 = (const float4*)memory;
    float4* __restrict__ out4 = (float4*)newmem;

    const size_t base = ((size_t)b * Nq + n0 + hw) * (Mq / 4) + l16;

    // ---- Phase A: batch all loads (max MLP) ----
    float4 m[4];
#pragma unroll
    for (int r = 0; r < 4; r++)
        m[r] = __ldcs(&mem4[base + (size_t)r * 32 * (Mq / 4)]);

    // ---- Phase B: all stores (independent of shuffle chains) ----
#pragma unroll
    for (int r = 0; r < 4; r++) {
        const float ww = sh_ww[hw + 32 * r];
        float4 o4;
        o4.x = m[r].x + ww * kv.x;
        o4.y = m[r].y + ww * kv.y;
        o4.z = m[r].z + ww * kv.z;
        o4.w = m[r].w + ww * kv.w;
        __stcs(&out4[base + (size_t)r * 32 * (Mq / 4)], o4);
    }

    // ---- Phase C: reductions -> sim ----
#pragma unroll
    for (int r = 0; r < 4; r++) {
        float dot = m[r].x * kv.x + m[r].y * kv.y + m[r].z * kv.z + m[r].w * kv.w;
        float nrm = m[r].x * m[r].x + m[r].y * m[r].y + m[r].z * m[r].z + m[r].w * m[r].w;
#pragma unroll
        for (int s = 8; s > 0; s >>= 1) {
            dot += __shfl_xor_sync(0xffffffffu, dot, s);
            nrm += __shfl_xor_sync(0xffffffffu, nrm, s);
        }
        if (l16 == 0)
            sh_sim[hw + 32 * r] = dot / (knorm * sqrtf(nrm) + EPSq);
    }
    __syncthreads();

    if (tid < 32)
        ((float4*)(g_sim + (size_t)b * Nq + n0))[tid] =
            ((const float4*)sh_sim)[tid];
}

// ---------------- kernel 3: softmax + w_u + top-4 smallest (w_lu) ---------------
__global__ void __launch_bounds__(1024, 1)
ntm_softmax_topk_kernel(const float* __restrict__ w_prev,
                        float* __restrict__ out) {
    const int b = blockIdx.x;
    const int tid = threadIdx.x;
    const int warp = tid >> 5;
    const int lane = tid & 31;

    __shared__ float sh_f[32];
    __shared__ unsigned long long sh_u[32];
    __shared__ float s_mx, s_sum;
    __shared__ unsigned long long s_win;
    __shared__ int s_chosen[4];

    const float beta = g_beta[b];
    const float gv   = g_gate[b];
    const float* __restrict__ simp = g_sim + (size_t)b * Nq;

    float sim[16];
    float lmax = -FLT_MAX;
#pragma unroll
    for (int j = 0; j < 16; j++) {
        const float s = simp[j * 1024 + tid];
        sim[j] = s;
        lmax = fmaxf(lmax, beta * s);
    }
#pragma unroll
    for (int s = 16; s > 0; s >>= 1)
        lmax = fmaxf(lmax, __shfl_xor_sync(0xffffffffu, lmax, s));
    if (lane == 0) sh_f[warp] = lmax;
    __syncthreads();
    if (tid < 32) {
        float v = sh_f[tid];
#pragma unroll
        for (int s = 16; s > 0; s >>= 1)
            v = fmaxf(v, __shfl_xor_sync(0xffffffffu, v, s));
        if (tid == 0) s_mx = v;
    }
    __syncthreads();
    const float mx = s_mx;

    float e[16];
    float lsum = 0.0f;
#pragma unroll
    for (int j = 0; j < 16; j++) {
        e[j] = expf(beta * sim[j] - mx);
        lsum += e[j];
    }
#pragma unroll
    for (int s = 16; s > 0; s >>= 1)
        lsum += __shfl_xor_sync(0xffffffffu, lsum, s);
    if (lane == 0) sh_f[warp] = lsum;
    __syncthreads();
    if (tid < 32) {
        float v = sh_f[tid];
#pragma unroll
        for (int s = 16; s > 0; s >>= 1)
            v += __shfl_xor_sync(0xffffffffu, v, s);
        if (tid == 0) s_sum = v;
    }
    __syncthreads();
    const float inv = 1.0f / s_sum;

    const float* __restrict__ wup  = w_prev + (size_t)b * 3 * Nq;
    const float* __restrict__ wrp  = wup + Nq;
    const float* __restrict__ wlup = wup + 2 * Nq;
    float* __restrict__ w_u_out  = out + (size_t)b * 3 * Nq;
    float* __restrict__ w_r_out  = w_u_out + Nq;
    float* __restrict__ w_lu_out = w_u_out + 2 * Nq;

    unsigned long long tk[4] = {~0ULL, ~0ULL, ~0ULL, ~0ULL};

#pragma unroll
    for (int j = 0; j < 16; j++) {
        const int n = j * 1024 + tid;
        const float wr = e[j] * inv;
        const float ww = gv * wrp[n] + (1.0f - gv) * wlup[n];
        const float wu = GAMMAq * wup[n] + wr + ww;
        w_r_out[n] = wr;
        w_u_out[n] = wu;

        const unsigned long long key =
            ((unsigned long long)__float_as_uint(wu) << 32) | (unsigned int)n;
        if (key < tk[3]) {
            tk[3] = key;
#pragma unroll
            for (int q = 3; q > 0; q--) {
                if (tk[q] < tk[q - 1]) {
                    unsigned long long t = tk[q]; tk[q] = tk[q - 1]; tk[q - 1] = t;
                }
            }
        }
    }

    for (int round = 0; round < 4; round++) {
        unsigned long long my = tk[0];
#pragma unroll
        for (int s = 16; s > 0; s >>= 1) {
            const unsigned long long o = __shfl_xor_sync(0xffffffffu, my, s);
            if (o < my) my = o;
        }
        if (lane == 0) sh_u[warp] = my;
        __syncthreads();
        if (tid < 32) {
            unsigned long long v = sh_u[tid];
#pragma unroll
            for (int s = 16; s > 0; s >>= 1) {
                const unsigned long long o = __shfl_xor_sync(0xffffffffu, v, s);
                if (o < v) v = o;
            }
            if (tid == 0) s_win = v;
        }
        __syncthreads();
        const unsigned long long win = s_win;
        if (tid == 0) s_chosen[round] = (int)(unsigned int)(win & 0xffffffffu);
        if (tk[0] == win) {
            tk[0] = tk[1]; tk[1] = tk[2]; tk[2] = tk[3]; tk[3] = ~0ULL;
        }
        __syncthreads();
    }

    const int c0 = s_chosen[0], c1 = s_chosen[1], c2 = s_chosen[2], c3 = s_chosen[3];
#pragma unroll
    for (int j = 0; j < 16; j++) {
        const int n = j * 1024 + tid;
        w_lu_out[n] = (n == c0 || n == c1 || n == c2 || n == c3) ? 1.0f : 0.0f;
    }
}

// ---------------- launch ----------------
extern "C" void kernel_launch(void* const* d_in, const int* in_sizes, int n_in,
                              void* d_out, int out_size) {
    const float* emb    = (const float*)d_in[0];  // (64, 256)
    const float* w_prev = (const float*)d_in[1];  // (64, 3, 16384)
    const float* memory = (const float*)d_in[2];  // (64, 16384, 64)
    const float* W      = (const float*)d_in[3];  // (66, 256)
    const float* bias   = (const float*)d_in[4];  // (66,)
    float* out = (float*)d_out;  // [w (64*3*16384) | new_memory (64*16384*64)]

    const int nwarps = Bq * NOUT;                 // 4224
    const int nblk1 = (nwarps * 32 + 255) / 256;  // 528
    ntm_proj_kernel<<<nblk1, 256>>>(emb, W, bias);

    dim3 grid2(Nq / 128, Bq);
    ntm_stream_kernel<<<grid2, 512>>>(memory, w_prev, out);

    ntm_softmax_topk_kernel<<<Bq, 1024>>>(w_prev, out);
}

// round 5
// speedup vs baseline: 1.1236x; 1.0168x over previous
#include <cuda_runtime.h>
#include <math.h>
#include <float.h>

#define Bq 64
#define Nq 16384
#define Mq 64
#define Cq 256
#define GAMMAq 0.95f
#define EPSq 1e-16f
#define NOUT 66   // M + 2
#define CHUNKS 128  // K2 grid.x = Nq/128

// ---------------- scratch (static device globals; no allocation) ----------------
__device__ float g_k[Bq * Mq];
__device__ float g_beta[Bq];
__device__ float g_gate[Bq];
__device__ float g_E[(size_t)Bq * Nq];             // exp(beta*(sim-1))
__device__ float g_psum[Bq * CHUNKS];              // per-K2-block partial sums of E
__device__ unsigned long long g_cand[Bq * 16];     // 4 chunks x 4 candidate keys

// ---------------- kernel 1: projection, warp per (batch, output) ----------------
__global__ void ntm_proj_kernel(const float* __restrict__ emb,
                                const float* __restrict__ W,
                                const float* __restrict__ bias) {
    const int wglob = (blockIdx.x * blockDim.x + threadIdx.x) >> 5;
    const int lane = threadIdx.x & 31;
    if (wglob >= Bq * NOUT) return;
    const int b = wglob / NOUT;
    const int o = wglob - b * NOUT;

    const float* __restrict__ e = emb + (size_t)b * Cq;
    const float* __restrict__ w = W + (size_t)o * Cq;

    float acc = 0.0f;
#pragma unroll
    for (int i = 0; i < 8; i++) {
        const int c = lane + 32 * i;
        acc = fmaf(__ldg(&e[c]), __ldg(&w[c]), acc);
    }
#pragma unroll
    for (int s = 16; s > 0; s >>= 1)
        acc += __shfl_xor_sync(0xffffffffu, acc, s);

    if (lane == 0) {
        acc += bias[o];
        if (o < Mq) {
            g_k[b * Mq + o] = acc;
        } else if (o == Mq) {
            g_beta[b] = (acc > 20.0f) ? acc : log1pf(expf(acc));
        } else {
            g_gate[b] = 1.0f / (1.0f + expf(-acc));
        }
    }
}

// ---------------- kernel 2: fused sim/exp + new_memory streaming pass -----------
// grid: (CHUNKS, Bq), block 512. Same phase A/B/C structure as R4 (proven 6.2TB/s).
// Epilogue now stores E = exp(beta*(sim-1)) (sim<=1 by Cauchy-Schwarz -> exact
// softmax shift, no global max needed) + deterministic per-block partial sum.
__global__ void __launch_bounds__(512)
ntm_stream_kernel(const float* __restrict__ memory,
                  const float* __restrict__ w_prev,
                  float* __restrict__ out) {
    const int b = blockIdx.y;
    const int n0 = blockIdx.x * 128;
    const int tid = threadIdx.x;
    const int hw = tid >> 4;
    const int l16 = tid & 15;

    __shared__ float4 sh_k4[16];
    __shared__ float sh_ww[128];
    __shared__ float sh_E[128];
    __shared__ float s_knorm;

    const float gv = g_gate[b];
    const float beta = g_beta[b];

    float kn = 0.0f;
    if (tid < 16) {
        const float4 k4 = ((const float4*)(g_k + (size_t)b * Mq))[tid];
        sh_k4[tid] = k4;
        kn = k4.x * k4.x + k4.y * k4.y + k4.z * k4.z + k4.w * k4.w;
    }
    if (tid < 32) {
#pragma unroll
        for (int s = 8; s > 0; s >>= 1)
            kn += __shfl_xor_sync(0xffffffffu, kn, s);
        if (tid == 0) s_knorm = sqrtf(kn);
    }
    if (tid < 128) {
        const int n = n0 + tid;
        const float wrp  = w_prev[((size_t)b * 3 + 1) * Nq + n];
        const float wlup = w_prev[((size_t)b * 3 + 2) * Nq + n];
        sh_ww[tid] = gv * wrp + (1.0f - gv) * wlup;
    }
    __syncthreads();

    const float knorm = s_knorm;
    const float4 kv = sh_k4[l16];
    float* __restrict__ newmem = out + (size_t)Bq * 3 * Nq;
    const float4* __restrict__ mem4 = (const float4*)memory;
    float4* __restrict__ out4 = (float4*)newmem;

    const size_t base = ((size_t)b * Nq + n0 + hw) * (Mq / 4) + l16;

    // Phase A: batch all loads
    float4 m[4];
#pragma unroll
    for (int r = 0; r < 4; r++)
        m[r] = __ldcs(&mem4[base + (size_t)r * 32 * (Mq / 4)]);

    // Phase B: all stores (independent of shuffle chains)
#pragma unroll
    for (int r = 0; r < 4; r++) {
        const float ww = sh_ww[hw + 32 * r];
        float4 o4;
        o4.x = m[r].x + ww * kv.x;
        o4.y = m[r].y + ww * kv.y;
        o4.z = m[r].z + ww * kv.z;
        o4.w = m[r].w + ww * kv.w;
        __stcs(&out4[base + (size_t)r * 32 * (Mq / 4)], o4);
    }

    // Phase C: reductions -> E
#pragma unroll
    for (int r = 0; r < 4; r++) {
        float dot = m[r].x * kv.x + m[r].y * kv.y + m[r].z * kv.z + m[r].w * kv.w;
        float nrm = m[r].x * m[r].x + m[r].y * m[r].y + m[r].z * m[r].z + m[r].w * m[r].w;
#pragma unroll
        for (int s = 8; s > 0; s >>= 1) {
            dot += __shfl_xor_sync(0xffffffffu, dot, s);
            nrm += __shfl_xor_sync(0xffffffffu, nrm, s);
        }
        if (l16 == 0) {
            const float sim = dot / (knorm * sqrtf(nrm) + EPSq);
            sh_E[hw + 32 * r] = expf(beta * (sim - 1.0f));
        }
    }
    __syncthreads();

    if (tid < 32) {
        const float4 e4 = ((const float4*)sh_E)[tid];
        ((float4*)(g_E + (size_t)b * Nq + n0))[tid] = e4;
        float ps = e4.x + e4.y + e4.z + e4.w;
#pragma unroll
        for (int s = 16; s > 0; s >>= 1)
            ps += __shfl_xor_sync(0xffffffffu, ps, s);
        if (tid == 0) g_psum[b * CHUNKS + blockIdx.x] = ps;
    }
}

// ---------------- kernel 3a: elementwise w_r/w_u + per-chunk top-4 --------------
// grid: 256 blocks (4 per batch), 1024 threads, 4 elems/thread.
__global__ void __launch_bounds__(1024, 1)
ntm_elem_kernel(const float* __restrict__ w_prev, float* __restrict__ out) {
    const int blk = blockIdx.x;
    const int b = blk >> 2;
    const int c = blk & 3;
    const int tid = threadIdx.x;
    const int warp = tid >> 5;
    const int lane = tid & 31;
    const int nbase = c * 4096;

    __shared__ float s_inv;
    __shared__ unsigned long long sh_keys[128];

    // reduce the 128 partial sums (deterministic fixed order)
    if (tid < 32) {
        const float* __restrict__ ps = g_psum + b * CHUNKS;
        float v = ps[tid] + ps[tid + 32] + ps[tid + 64] + ps[tid + 96];
#pragma unroll
        for (int s = 16; s > 0; s >>= 1)
            v += __shfl_xor_sync(0xffffffffu, v, s);
        if (tid == 0) s_inv = 1.0f / v;
    }
    __syncthreads();
    const float inv = s_inv;
    const float gv = g_gate[b];

    const float* __restrict__ Ep   = g_E + (size_t)b * Nq;
    const float* __restrict__ wup  = w_prev + (size_t)b * 3 * Nq;
    const float* __restrict__ wrp  = wup + Nq;
    const float* __restrict__ wlup = wup + 2 * Nq;
    float* __restrict__ w_u_out  = out + (size_t)b * 3 * Nq;
    float* __restrict__ w_r_out  = w_u_out + Nq;
    float* __restrict__ w_lu_out = w_u_out + 2 * Nq;

    unsigned long long tk[4] = {~0ULL, ~0ULL, ~0ULL, ~0ULL};

#pragma unroll
    for (int j = 0; j < 4; j++) {
        const int n = nbase + j * 1024 + tid;
        const float wr = Ep[n] * inv;
        const float ww = gv * wrp[n] + (1.0f - gv) * wlup[n];
        const float wu = GAMMAq * wup[n] + wr + ww;
        w_r_out[n] = wr;
        w_u_out[n] = wu;
        w_lu_out[n] = 0.0f;

        const unsigned long long key =
            ((unsigned long long)__float_as_uint(wu) << 32) | (unsigned int)n;
        if (key < tk[3]) {
            tk[3] = key;
#pragma unroll
            for (int q = 3; q > 0; q--) {
                if (tk[q] < tk[q - 1]) {
                    unsigned long long t = tk[q]; tk[q] = tk[q - 1]; tk[q - 1] = t;
                }
            }
        }
    }

    // per-warp top-4 via 4 rounds of shfl argmin + pop (no barriers)
#pragma unroll
    for (int round = 0; round < 4; round++) {
        unsigned long long v = tk[0];
#pragma unroll
        for (int s = 16; s > 0; s >>= 1) {
            const unsigned long long o = __shfl_xor_sync(0xffffffffu, v, s);
            if (o < v) v = o;
        }
        if (tk[0] == v) {  // unique key -> exactly one popper
            tk[0] = tk[1]; tk[1] = tk[2]; tk[2] = tk[3]; tk[3] = ~0ULL;
        }
        if (lane == 0) sh_keys[warp * 4 + round] = v;
    }
    __syncthreads();

    // warp 0: reduce 128 candidates -> block top-4
    if (warp == 0) {
        unsigned long long bk[4] = {~0ULL, ~0ULL, ~0ULL, ~0ULL};
#pragma unroll
        for (int j = 0; j < 4; j++) {
            const unsigned long long key = sh_keys[lane + 32 * j];
            if (key < bk[3]) {
                bk[3] = key;
#pragma unroll
                for (int q = 3; q > 0; q--) {
                    if (bk[q] < bk[q - 1]) {
                        unsigned long long t = bk[q]; bk[q] = bk[q - 1]; bk[q - 1] = t;
                    }
                }
            }
        }
#pragma unroll
        for (int round = 0; round < 4; round++) {
            unsigned long long v = bk[0];
#pragma unroll
            for (int s = 16; s > 0; s >>= 1) {
                const unsigned long long o = __shfl_xor_sync(0xffffffffu, v, s);
                if (o < v) v = o;
            }
            if (bk[0] == v) {
                bk[0] = bk[1]; bk[1] = bk[2]; bk[2] = bk[3]; bk[3] = ~0ULL;
            }
            if (lane == 0) g_cand[(b * 4 + c) * 4 + round] = v;
        }
    }
}

// ---------------- kernel 3b: finalize top-4 -> scatter w_lu ones ----------------
// 64 blocks x 32 threads. Top-4 of the 16 per-chunk candidates = global top-4.
__global__ void ntm_finalize_kernel(float* __restrict__ out) {
    const int b = blockIdx.x;
    const int lane = threadIdx.x;
    float* __restrict__ w_lu_out = out + ((size_t)b * 3 + 2) * Nq;

    unsigned long long key = (lane < 16) ? g_cand[b * 16 + lane] : ~0ULL;
#pragma unroll
    for (int round = 0; round < 4; round++) {
        unsigned long long v = key;
#pragma unroll
        for (int s = 16; s > 0; s >>= 1) {
            const unsigned long long o = __shfl_xor_sync(0xffffffffu, v, s);
            if (o < v) v = o;
        }
        if (key == v) key = ~0ULL;  // pop winner
        if (lane == round)
            w_lu_out[(int)(unsigned int)(v & 0xffffffffu)] = 1.0f;
    }
}

// ---------------- launch ----------------
extern "C" void kernel_launch(void* const* d_in, const int* in_sizes, int n_in,
                              void* d_out, int out_size) {
    const float* emb    = (const float*)d_in[0];  // (64, 256)
    const float* w_prev = (const float*)d_in[1];  // (64, 3, 16384)
    const float* memory = (const float*)d_in[2];  // (64, 16384, 64)
    const float* W      = (const float*)d_in[3];  // (66, 256)
    const float* bias   = (const float*)d_in[4];  // (66,)
    float* out = (float*)d_out;  // [w (64*3*16384) | new_memory (64*16384*64)]

    const int nwarps = Bq * NOUT;                 // 4224
    const int nblk1 = (nwarps * 32 + 255) / 256;  // 528
    ntm_proj_kernel<<<nblk1, 256>>>(emb, W, bias);

    dim3 grid2(CHUNKS, Bq);
    ntm_stream_kernel<<<grid2, 512>>>(memory, w_prev, out);

    ntm_elem_kernel<<<Bq * 4, 1024>>>(w_prev, out);
    ntm_finalize_kernel<<<Bq, 32>>>(out);
}